// round 1
// baseline (speedup 1.0000x reference)
#include <cuda_runtime.h>

#define KSEL 512
#define NTHREADS_SEL 1024
#define MAX_PER_THREAD 16
#define SPLITS 4
#define NEG_PER_SPLIT (KSEL / SPLITS)   // 128
#define CLAMP_HI 1000001.0f             // min(EF,1e6)+1 -> log = -log(eps)

__device__ float g_E[KSEL];        // exp() of the 512 largest score_neg values
__device__ float g_partials[256];  // per-block partial sums

__device__ __forceinline__ unsigned int f2key(float x) {
    unsigned int u = __float_as_uint(x);
    return (u & 0x80000000u) ? ~u : (u | 0x80000000u);  // order-preserving
}
__device__ __forceinline__ float key2f(unsigned int k) {
    unsigned int u = (k & 0x80000000u) ? (k ^ 0x80000000u) : ~k;
    return __uint_as_float(u);
}

// ---------------------------------------------------------------------------
// Kernel 1: exact top-512 selection of score_neg via 4-pass radix select,
// single block, keys register-resident. Writes exp(value) into g_E (any order;
// the downstream sum is order-independent).
// ---------------------------------------------------------------------------
__global__ void topk_select_kernel(const float* __restrict__ neg, int n) {
    __shared__ unsigned int bins[256];
    __shared__ unsigned int sh_prefix, sh_mask, sh_remaining;
    __shared__ unsigned int sh_c1, sh_c2;

    const int tid = threadIdx.x;
    unsigned int keys[MAX_PER_THREAD];
    int cnt = 0;
    for (int i = tid; i < n; i += NTHREADS_SEL) {
        if (cnt < MAX_PER_THREAD) keys[cnt] = f2key(neg[i]);
        cnt++;
    }
    if (cnt > MAX_PER_THREAD) cnt = MAX_PER_THREAD;  // n assumed <= 16384

    if (tid == 0) { sh_prefix = 0u; sh_mask = 0u; sh_remaining = KSEL; }
    __syncthreads();

    #pragma unroll
    for (int pass = 0; pass < 4; pass++) {
        const int shift = 24 - 8 * pass;
        if (tid < 256) bins[tid] = 0u;
        __syncthreads();
        const unsigned int prefix = sh_prefix, mask = sh_mask;
        #pragma unroll
        for (int c = 0; c < MAX_PER_THREAD; c++) {
            if (c < cnt) {
                const unsigned int k = keys[c];
                if ((k & mask) == prefix)
                    atomicAdd(&bins[(k >> shift) & 0xFFu], 1u);
            }
        }
        __syncthreads();
        if (tid == 0) {
            unsigned int rem = sh_remaining, cum = 0u;
            int b = 0;
            for (int i = 255; i >= 0; i--) {
                const unsigned int nb = bins[i];
                if (cum + nb >= rem) { b = i; break; }
                cum += nb;
            }
            sh_remaining = rem - cum;                       // still needed inside bin b
            sh_prefix = prefix | ((unsigned int)b << shift);
            sh_mask = mask | (0xFFu << shift);
        }
        __syncthreads();
    }

    const unsigned int T = sh_prefix;      // exact threshold key
    const unsigned int r = sh_remaining;   // # of ==T elements to take (>=1)
    if (tid == 0) { sh_c1 = 0u; sh_c2 = 0u; }
    __syncthreads();

    const int base_eq = KSEL - (int)r;     // == count(keys > T) by construction
    #pragma unroll
    for (int c = 0; c < MAX_PER_THREAD; c++) {
        if (c < cnt) {
            const unsigned int k = keys[c];
            int slot = -1;
            if (k > T) {
                slot = (int)atomicAdd(&sh_c1, 1u);
            } else if (k == T) {
                const unsigned int idx = atomicAdd(&sh_c2, 1u);
                if (idx < r) slot = base_eq + (int)idx;     // ties: equal values, any subset
            }
            if (slot >= 0) g_E[slot] = __expf(key2f(k));
        }
    }
}

// ---------------------------------------------------------------------------
// Kernel 2: sum_{i,j} log1p(min(E_j * exp(-pos_i), 1e6))
// Grid: (ceil(n_pos/256), SPLITS). Each thread handles one pos row's
// 128-element split. Group-of-4 product => 1 LG2 per 4 elements.
// ---------------------------------------------------------------------------
__global__ void pauc_main_kernel(const float* __restrict__ pos, int n_pos) {
    __shared__ float sE[KSEL];
    __shared__ float red[8];

    for (int i = threadIdx.x; i < KSEL; i += blockDim.x) sE[i] = g_E[i];
    __syncthreads();

    const int i = blockIdx.x * blockDim.x + threadIdx.x;   // pos row
    const int s = blockIdx.y;                              // split id
    float acc = 0.0f;
    if (i < n_pos) {
        const float F = __expf(-pos[i]);
        const float4* e4 = reinterpret_cast<const float4*>(&sE[s * NEG_PER_SPLIT]);
        #pragma unroll
        for (int grp = 0; grp < NEG_PER_SPLIT / 4; grp++) {
            const float4 e = e4[grp];                      // uniform across warp: broadcast
            float t0 = fminf(__fmaf_rn(e.x, F, 1.0f), CLAMP_HI);
            float t1 = fminf(__fmaf_rn(e.y, F, 1.0f), CLAMP_HI);
            float t2 = fminf(__fmaf_rn(e.z, F, 1.0f), CLAMP_HI);
            float t3 = fminf(__fmaf_rn(e.w, F, 1.0f), CLAMP_HI);
            acc += __logf((t0 * t1) * (t2 * t3));          // <= 1e24, no overflow
        }
    }

    // deterministic block reduction
    #pragma unroll
    for (int off = 16; off > 0; off >>= 1)
        acc += __shfl_down_sync(0xffffffffu, acc, off);
    if ((threadIdx.x & 31) == 0) red[threadIdx.x >> 5] = acc;
    __syncthreads();
    if (threadIdx.x == 0) {
        float t = 0.0f;
        const int nw = (int)blockDim.x >> 5;
        for (int w = 0; w < nw; w++) t += red[w];
        g_partials[blockIdx.y * gridDim.x + blockIdx.x] = t;
    }
}

// ---------------------------------------------------------------------------
// Kernel 3: reduce per-block partials -> scalar output
// ---------------------------------------------------------------------------
__global__ void finalize_kernel(float* out, float inv_denom, int nparts) {
    __shared__ float red[4];
    const int tid = threadIdx.x;  // 128 threads
    float a = 0.0f;
    for (int i = tid; i < nparts; i += 128) a += g_partials[i];
    #pragma unroll
    for (int off = 16; off > 0; off >>= 1)
        a += __shfl_down_sync(0xffffffffu, a, off);
    if ((tid & 31) == 0) red[tid >> 5] = a;
    __syncthreads();
    if (tid == 0)
        out[0] = (red[0] + red[1] + red[2] + red[3]) * inv_denom;
}

// ---------------------------------------------------------------------------
extern "C" void kernel_launch(void* const* d_in, const int* in_sizes, int n_in,
                              void* d_out, int out_size) {
    const float* neg = (const float*)d_in[0];   // score_neg [16384]
    const float* pos = (const float*)d_in[1];   // score_pos [8192]
    const int n_neg = in_sizes[0];
    const int n_pos = in_sizes[1];

    topk_select_kernel<<<1, NTHREADS_SEL>>>(neg, n_neg);

    const int bx = (n_pos + 255) / 256;         // 32
    dim3 grid(bx, SPLITS, 1);                   // 128 blocks total
    pauc_main_kernel<<<grid, 256>>>(pos, n_pos);

    const float inv_denom = (float)(1.0 / ((double)n_neg * (double)n_pos)); // 2^-27 exact
    finalize_kernel<<<1, 128>>>((float*)d_out, inv_denom, bx * SPLITS);
}